// round 5
// baseline (speedup 1.0000x reference)
#include <cuda_runtime.h>

#define NB 4096
#define FS 66    // feature-major stride: [128 feats][64 nodes + 2 pad]
#define AS 66    // transposed-adjacency stride
#define SS 68    // score-tile stride
#define NTHR 512

// ---------- packed fp32x2 helpers (sm_103a FFMA2 path) ----------
static __device__ __forceinline__ unsigned long long pack2(float x){
    unsigned long long r;
    asm("mov.b64 %0, {%1, %1};" : "=l"(r) : "f"(x));
    return r;
}
static __device__ __forceinline__ void fma2(unsigned long long& d, unsigned long long a, unsigned long long b){
    asm("fma.rn.f32x2 %0, %1, %2, %0;" : "+l"(d) : "l"(a), "l"(b));
}
static __device__ __forceinline__ float2 unpack2(unsigned long long v){
    float2 r;
    asm("mov.b64 {%0, %1}, %2;" : "=f"(r.x), "=f"(r.y) : "l"(v));
    return r;
}

// ================= W-GEMM: Yt[c][r] = sum_k W[k][c] * Xt[k][r], K=128 =================
// Xt feature-major [128][FS] in smem (lane = node, coalesced).
// W global row-major [128][128]; warp owns 8 cols -> uniform 2x16B LDG per k.
// MODE: 0 plain, 1 relu(v+bias), 2 relu(v+bias)*laneScale[r], 3 accumulate, 4 v+bias
template<int MODE>
static __device__ __forceinline__ void mmW(
    const float* __restrict__ Xt, const float* __restrict__ W,
    const float* __restrict__ bias, const float* __restrict__ laneScale,
    float* __restrict__ Yt)
{
    const int wid = threadIdx.x >> 5, lane = threadIdx.x & 31;
    const int c0 = wid << 3;   // 8 cols per warp
    unsigned long long acc[2][4];
#pragma unroll
    for (int r = 0; r < 2; ++r)
#pragma unroll
        for (int p = 0; p < 4; ++p) acc[r][p] = 0ull;
#pragma unroll 8
    for (int k = 0; k < 128; ++k){
        float xa = Xt[k*FS + lane];
        float xb = Xt[k*FS + lane + 32];
        ulonglong2 wA = *(const ulonglong2*)(W + k*128 + c0);      // cols c0..c0+3
        ulonglong2 wB = *(const ulonglong2*)(W + k*128 + c0 + 4);  // cols c0+4..c0+7
        unsigned long long A0 = pack2(xa), A1 = pack2(xb);
        fma2(acc[0][0], wA.x, A0); fma2(acc[0][1], wA.y, A0);
        fma2(acc[0][2], wB.x, A0); fma2(acc[0][3], wB.y, A0);
        fma2(acc[1][0], wA.x, A1); fma2(acc[1][1], wA.y, A1);
        fma2(acc[1][2], wB.x, A1); fma2(acc[1][3], wB.y, A1);
    }
    float bb[8];
    if (MODE == 1 || MODE == 2 || MODE == 4){
#pragma unroll
        for (int p = 0; p < 4; ++p){
            float2 b2 = *(const float2*)(bias + c0 + 2*p);
            bb[2*p] = b2.x; bb[2*p+1] = b2.y;
        }
    }
    float sA = 1.f, sB = 1.f;
    if (MODE == 2){ sA = laneScale[lane]; sB = laneScale[lane + 32]; }
#pragma unroll
    for (int r = 0; r < 2; ++r){
        const int row = lane + r*32;
        const float sc = r ? sB : sA;
#pragma unroll
        for (int p = 0; p < 4; ++p){
            float2 v = unpack2(acc[r][p]);
            if (MODE == 1 || MODE == 2 || MODE == 4){ v.x += bb[2*p]; v.y += bb[2*p+1]; }
            if (MODE == 1 || MODE == 2){ v.x = fmaxf(v.x, 0.f); v.y = fmaxf(v.y, 0.f); }
            if (MODE == 2){ v.x *= sc; v.y *= sc; }
            float* y0 = Yt + (c0 + 2*p)*FS + row;
            float* y1 = Yt + (c0 + 2*p + 1)*FS + row;
            if (MODE == 3){ v.x += *y0; v.y += *y1; }
            *y0 = v.x; *y1 = v.y;
        }
    }
}

// ===== uniform(smem) x coalesced(smem): Yt[d][i] (+)= sum_j U[d][j] * C[j][i], K=64 =====
// U feature-major stride FS (uniform per warp: warp owns 8 d's); C row-major [64][cstr].
template<int ACC>
static __device__ __forceinline__ void mmU(
    const float* __restrict__ U, const float* __restrict__ C, int cstr,
    float* __restrict__ Yt)
{
    const int wid = threadIdx.x >> 5, lane = threadIdx.x & 31;
    const int d0 = wid << 3;
    unsigned long long acc[8];
#pragma unroll
    for (int q = 0; q < 8; ++q) acc[q] = 0ull;
#pragma unroll 4
    for (int j = 0; j < 64; ++j){
        unsigned long long cv = *(const unsigned long long*)(C + j*cstr + 2*lane);
#pragma unroll
        for (int q = 0; q < 8; ++q){
            unsigned long long uq = pack2(U[(d0 + q)*FS + j]);
            fma2(acc[q], cv, uq);
        }
    }
#pragma unroll
    for (int q = 0; q < 8; ++q){
        float2 v = unpack2(acc[q]);
        float* y = Yt + (d0 + q)*FS + 2*lane;
        if (ACC){ v.x += y[0]; v.y += y[1]; }
        *(float2*)y = v;
    }
}

// ===== S-GEMM: S[i][j] = sum_d Tt[d][i] * Et[d][j], K=128 =====
static __device__ __forceinline__ void mmS(
    const float* __restrict__ Tt, const float* __restrict__ Et, float* __restrict__ S)
{
    const int wid = threadIdx.x >> 5, lane = threadIdx.x & 31;
    const int i0 = wid << 2;   // 4 rows i per warp
    unsigned long long acc[4];
#pragma unroll
    for (int q = 0; q < 4; ++q) acc[q] = 0ull;
#pragma unroll 4
    for (int d = 0; d < 128; ++d){
        unsigned long long ev = *(const unsigned long long*)(Et + d*FS + 2*lane);
#pragma unroll
        for (int q = 0; q < 4; ++q){
            unsigned long long tq = pack2(Tt[d*FS + i0 + q]);
            fma2(acc[q], ev, tq);
        }
    }
#pragma unroll
    for (int q = 0; q < 4; ++q){
        float2 v = unpack2(acc[q]);
        *(float2*)(S + (i0 + q)*SS + 2*lane) = v;
    }
}

// ===== SimGNN attention pooling on feature-major Xt [128][FS] (mask all-ones) =====
static __device__ __forceinline__ void pool(
    const float* __restrict__ Xt, const float* __restrict__ Wp, float* __restrict__ out,
    float* __restrict__ mvec, float* __restrict__ ctxv, float* __restrict__ scores,
    float* __restrict__ gvec)
{
    const int t = threadIdx.x;
    const int wid = t >> 5, lane = t & 31;
#pragma unroll
    for (int q = 0; q < 8; ++q){
        int d = wid*8 + q;
        float s = Xt[d*FS + lane] + Xt[d*FS + lane + 32];
#pragma unroll
        for (int o = 16; o; o >>= 1) s += __shfl_xor_sync(0xffffffffu, s, o);
        if (lane == 0) mvec[d] = s * (1.0f / 64.0f);
    }
    __syncthreads();
    if (t < 128){
        float s = 0.f;
#pragma unroll 8
        for (int d = 0; d < 128; ++d) s += mvec[d] * Wp[d*128 + t];
        ctxv[t] = tanhf(s);
    }
    __syncthreads();
    if (t < 64){
        float s = 0.f;
#pragma unroll 8
        for (int d = 0; d < 128; ++d) s += Xt[d*FS + t] * ctxv[d];
        scores[t] = 1.0f / (1.0f + __expf(-s));
    }
    __syncthreads();
#pragma unroll
    for (int q = 0; q < 8; ++q){
        int c = wid*8 + q;
        float s = Xt[c*FS + lane]*scores[lane] + Xt[c*FS + lane + 32]*scores[lane + 32];
#pragma unroll
        for (int o = 16; o; o >>= 1) s += __shfl_xor_sync(0xffffffffu, s, o);
        if (lane == 0) gvec[c] = s;
    }
    __syncthreads();
    if (t < 32) *(float4*)(out + 4*t) = *(const float4*)(gvec + 4*t);
}

__global__ void __launch_bounds__(NTHR, 1) CGFA_19533511262348_kernel(
    const float* __restrict__ A_src, const float* __restrict__ emb_src,
    const float* __restrict__ A_dst, const float* __restrict__ emb_dst,
    const float* __restrict__ Wa, const float* __restrict__ ba,
    const float* __restrict__ Wu, const float* __restrict__ bu,
    const float* __restrict__ Aff, const float* __restrict__ Wc, const float* __restrict__ bc,
    const float* __restrict__ Wp1, const float* __restrict__ Wp2,
    float* __restrict__ out)
{
    extern __shared__ float smf[];
    float* E1t    = smf;                 // 128*FS
    float* E2t    = E1t + 128*FS;        // 128*FS
    float* Tt     = E2t + 128*FS;        // 128*FS scratch (Wa-out / Aff-out / att-out)
    float* Xt     = Tt  + 128*FS;        // 128*FS scratch (input / new-features)
    float* Ast    = Xt  + 128*FS;        // 64*AS, transposed adjacency: Ast[j][i] = A[i][j]
    float* S      = Ast + 64*AS;         // 64*SS (raw scores -> col-softmax in place)
    float* P1t    = S   + 64*SS;         // 64*SS (row-softmax, transposed [j][i])
    float* colInv = P1t + 64*SS;         // 64
    float* rmax   = colInv + 64;
    float* rsumI  = rmax + 64;
    float* cmax   = rsumI + 64;
    float* csumI  = cmax + 64;
    float* mvec   = csumI + 64;          // 128
    float* ctxv   = mvec + 128;          // 128
    float* gvec   = ctxv + 128;          // 128
    float* scores = gvec + 128;          // 64

    const int b = blockIdx.x;
    const int t = threadIdx.x;
    const int wid = t >> 5, lane = t & 31;

    // ===== Siamese intra-graph conv (feature-major) =====
    for (int g = 0; g < 2; ++g){
        const float* Ain = g ? A_dst : A_src;
        const float* Ein = g ? emb_dst : emb_src;
        float* Eout = g ? E2t : E1t;
        // load emb row-major from global, store transposed feature-major
#pragma unroll
        for (int rr = 0; rr < 4; ++rr){
            int r = wid*4 + rr;
            float4 v = *(const float4*)(Ein + ((size_t)b*64 + r)*128 + lane*4);
            Xt[(4*lane + 0)*FS + r] = v.x;
            Xt[(4*lane + 1)*FS + r] = v.y;
            Xt[(4*lane + 2)*FS + r] = v.z;
            Xt[(4*lane + 3)*FS + r] = v.w;
        }
        // load A coalesced, store TRANSPOSED: Ast[j][i] = A[i][j]
        for (int e = t*4; e < 64*64; e += NTHR*4){
            int i = e >> 6, j = e & 63;
            float4 v = *(const float4*)(Ain + (size_t)b*64*64 + e);
            Ast[(j + 0)*AS + i] = v.x;
            Ast[(j + 1)*AS + i] = v.y;
            Ast[(j + 2)*AS + i] = v.z;
            Ast[(j + 3)*AS + i] = v.w;
        }
        __syncthreads();
        // colsum of A = row-sum of Ast, warp-parallel coalesced
#pragma unroll
        for (int r = 0; r < 4; ++r){
            int j = wid*4 + r;
            float s = Ast[j*AS + lane] + Ast[j*AS + lane + 32];
#pragma unroll
            for (int o = 16; o; o >>= 1) s += __shfl_xor_sync(0xffffffffu, s, o);
            if (lane == 0) colInv[j] = 1.0f / fmaxf(s, 1e-12f);
        }
        __syncthreads();
        mmW<1>(Xt, Wu, bu, nullptr, Eout);      // Eout = relu(x@Wu+bu)   [feat-major]
        mmW<2>(Xt, Wa, ba, colInv, Tt);         // Tt = relu(x@Wa+ba) * colInv[node]
        __syncthreads();
        mmU<1>(Tt, Ast, AS, Eout);              // Eout += (A @ T): sum_j T[j][d]*A[i][j]
        __syncthreads();
    }

    // ===== affinity: S = (E1 @ Aff) @ E2^T =====
    mmW<0>(E1t, Aff, nullptr, nullptr, Tt);     // Tt[c][r] = (E1@Aff)[r,c]
    __syncthreads();
    mmS(Tt, E2t, S);                            // S[i][j]
    __syncthreads();

    // ===== bidirectional softmax stats (masks all true) =====
#pragma unroll
    for (int r = 0; r < 4; ++r){
        int i = wid*4 + r;
        float a = S[i*SS + lane], bv = S[i*SS + lane + 32];
        float mx = fmaxf(a, bv);
#pragma unroll
        for (int o = 16; o; o >>= 1) mx = fmaxf(mx, __shfl_xor_sync(0xffffffffu, mx, o));
        float s = __expf(a - mx) + __expf(bv - mx);
#pragma unroll
        for (int o = 16; o; o >>= 1) s += __shfl_xor_sync(0xffffffffu, s, o);
        if (lane == 0){ rmax[i] = mx; rsumI[i] = 1.0f / s; }
    }
#pragma unroll
    for (int r = 0; r < 4; ++r){
        int j = wid*4 + r;
        float a = S[lane*SS + j], bv = S[(lane + 32)*SS + j];
        float mx = fmaxf(a, bv);
#pragma unroll
        for (int o = 16; o; o >>= 1) mx = fmaxf(mx, __shfl_xor_sync(0xffffffffu, mx, o));
        float s = __expf(a - mx) + __expf(bv - mx);
#pragma unroll
        for (int o = 16; o; o >>= 1) s += __shfl_xor_sync(0xffffffffu, s, o);
        if (lane == 0){ cmax[j] = mx; csumI[j] = 1.0f / s; }
    }
    __syncthreads();
    for (int e = t; e < 4096; e += NTHR){
        int i = e >> 6, j = e & 63;
        float v = S[i*SS + j];
        P1t[j*SS + i] = __expf(v - rmax[i]) * rsumI[i];   // row-softmax, transposed [j][i]
        S[i*SS + j]   = __expf(v - cmax[j]) * csumI[j];   // col-softmax, in place
    }
    __syncthreads();

    // ===== new1 = [E1, softmax(S) @ E2] @ Wc + bc ; pool -> g1 =====
    mmU<0>(E2t, P1t, SS, Tt);                  // att1[i][d] = sum_m P1[i][m]*E2[m][d]
    __syncthreads();
    mmW<4>(E1t, Wc, bc, nullptr, Xt);          // E1 @ Wc[:128] + bc
    mmW<3>(Tt,  Wc + 128*128, nullptr, nullptr, Xt);  // += att1 @ Wc[128:]
    __syncthreads();
    pool(Xt, Wp1, out + (size_t)b*128, mvec, ctxv, scores, gvec);
    __syncthreads();

    // ===== new2 = [E2, softmax(S^T) @ E1] @ Wc + bc ; pool -> g2 =====
    mmU<0>(E1t, S, SS, Tt);                    // att2[i][d] = sum_m P2[i][m]*E1[m][d]
    __syncthreads();
    mmW<4>(E2t, Wc, bc, nullptr, Xt);
    mmW<3>(Tt,  Wc + 128*128, nullptr, nullptr, Xt);
    __syncthreads();
    pool(Xt, Wp2, out + (size_t)(NB + b)*128, mvec, ctxv, scores, gvec);
}

extern "C" void kernel_launch(void* const* d_in, const int* in_sizes, int n_in,
                              void* d_out, int out_size)
{
    (void)in_sizes; (void)n_in; (void)out_size;
    const float* A_src   = (const float*)d_in[0];
    const float* emb_src = (const float*)d_in[1];
    // d_in[2] = mask_src (all ones, unused)
    const float* A_dst   = (const float*)d_in[3];
    const float* emb_dst = (const float*)d_in[4];
    // d_in[5] = mask_dst (all ones, unused)
    const float* Wa  = (const float*)d_in[6];
    const float* ba  = (const float*)d_in[7];
    const float* Wu  = (const float*)d_in[8];
    const float* bu  = (const float*)d_in[9];
    const float* Aff = (const float*)d_in[10];
    const float* Wc  = (const float*)d_in[11];
    const float* bc  = (const float*)d_in[12];
    const float* Wp1 = (const float*)d_in[13];
    const float* Wp2 = (const float*)d_in[14];
    float* out = (float*)d_out;

    const int smem_bytes = (128*FS*4 + 64*AS + 64*SS*2 + 64*5 + 128*3 + 64) * (int)sizeof(float);
    cudaFuncSetAttribute(CGFA_19533511262348_kernel,
                         cudaFuncAttributeMaxDynamicSharedMemorySize, smem_bytes);
    CGFA_19533511262348_kernel<<<NB, NTHR, smem_bytes>>>(
        A_src, emb_src, A_dst, emb_dst,
        Wa, ba, Wu, bu, Aff, Wc, bc, Wp1, Wp2, out);
}

// round 6
// speedup vs baseline: 1.3106x; 1.3106x over previous
#include <cuda_runtime.h>

#define NB 4096
#define XS 132   // row stride for 64x128 fp32 tiles
#define SS 68    // row stride for 64x64 score tiles
#define NTHR 256
#define WST 2048 // floats per W stage (16 rows x 128 cols)

// ---------- packed fp32x2 helpers (sm_103a FFMA2 path) ----------
static __device__ __forceinline__ unsigned long long pack2(float x){
    unsigned long long r;
    asm("mov.b64 %0, {%1, %1};" : "=l"(r) : "f"(x));
    return r;
}
static __device__ __forceinline__ void fma2(unsigned long long& d, unsigned long long a, unsigned long long b){
    asm("fma.rn.f32x2 %0, %1, %2, %0;" : "+l"(d) : "l"(a), "l"(b));
}
static __device__ __forceinline__ float2 unpack2(unsigned long long v){
    float2 r;
    asm("mov.b64 {%0, %1}, %2;" : "=f"(r.x), "=f"(r.y) : "l"(v));
    return r;
}

// ---------- cp.async helpers ----------
static __device__ __forceinline__ void cp16(unsigned dst, const float* src){
    asm volatile("cp.async.cg.shared.global [%0], [%1], 16;" :: "r"(dst), "l"(src));
}
static __device__ __forceinline__ void cpcommit(){
    asm volatile("cp.async.commit_group;");
}

// ======= staged W-GEMM: Y[r][c] = sum_k X[r][k]*W[k][c], K=128, X/Y stride XS ======
// W streamed from global via cp.async triple buffer. Warp = 8 rows x 128 cols.
// MODE: 0 plain, 1 relu(v+b), 2 relu(v+b)*rowScale[r], 3 accumulate, 4 v+b
template<int MODE>
static __device__ __forceinline__ void mmWstage(
    const float* __restrict__ Xp, const float* __restrict__ Wg,
    const float* __restrict__ bias, const float* __restrict__ rowScale,
    float* __restrict__ Yp, float* __restrict__ Wbuf, unsigned wbase)
{
    const int t = threadIdx.x;
    const int wid = t >> 5, lane = t & 31;
    const int r0 = wid << 3, c = lane << 2;

    // prologue: stage 0 -> buf0, stage 1 -> buf1
    {
        const float* gp = Wg;
        unsigned sp = wbase;
        cp16(sp + (unsigned)t*16u, gp + t*4);
        cp16(sp + (unsigned)(t+256)*16u, gp + (t+256)*4);
        cpcommit();
        gp = Wg + WST; sp = wbase + WST*4u;
        cp16(sp + (unsigned)t*16u, gp + t*4);
        cp16(sp + (unsigned)(t+256)*16u, gp + (t+256)*4);
        cpcommit();
    }

    unsigned long long acc[8][2];
#pragma unroll
    for (int r = 0; r < 8; ++r){ acc[r][0] = 0ull; acc[r][1] = 0ull; }

#pragma unroll 1
    for (int s = 0; s < 8; ++s){
        if (s < 7) asm volatile("cp.async.wait_group 1;" ::: "memory");
        else       asm volatile("cp.async.wait_group 0;" ::: "memory");
        __syncthreads();
        if (s + 2 < 8){
            int b = (s + 2) % 3;
            const float* gp = Wg + (s + 2)*WST;
            unsigned sp = wbase + (unsigned)(b*WST)*4u;
            cp16(sp + (unsigned)t*16u, gp + t*4);
            cp16(sp + (unsigned)(t+256)*16u, gp + (t+256)*4);
            cpcommit();
        }
        const float* Wb = Wbuf + (s % 3)*WST;
        const int kb = s*16;
#pragma unroll
        for (int kk = 0; kk < 16; kk += 4){
            float4 xq[8];
#pragma unroll
            for (int r = 0; r < 8; ++r)
                xq[r] = *(const float4*)(Xp + (r0 + r)*XS + kb + kk);
#pragma unroll
            for (int u = 0; u < 4; ++u){
                ulonglong2 w = *(const ulonglong2*)(Wb + (kk + u)*128 + c);
#pragma unroll
                for (int r = 0; r < 8; ++r){
                    float xv = (u == 0) ? xq[r].x : (u == 1) ? xq[r].y : (u == 2) ? xq[r].z : xq[r].w;
                    unsigned long long xx = pack2(xv);
                    fma2(acc[r][0], w.x, xx);
                    fma2(acc[r][1], w.y, xx);
                }
            }
        }
    }
    __syncthreads();   // protect Wbuf before any subsequent staging call

    float4 bb = make_float4(0.f, 0.f, 0.f, 0.f);
    if (MODE == 1 || MODE == 2 || MODE == 4) bb = *(const float4*)(bias + c);
#pragma unroll
    for (int r = 0; r < 8; ++r){
        float2 p0 = unpack2(acc[r][0]);
        float2 p1 = unpack2(acc[r][1]);
        float vx = p0.x + bb.x, vy = p0.y + bb.y, vz = p1.x + bb.z, vw = p1.y + bb.w;
        if (MODE == 1 || MODE == 2){
            vx = fmaxf(vx, 0.f); vy = fmaxf(vy, 0.f);
            vz = fmaxf(vz, 0.f); vw = fmaxf(vw, 0.f);
        }
        if (MODE == 2){
            float sc = rowScale[r0 + r];
            vx *= sc; vy *= sc; vz *= sc; vw *= sc;
        }
        float* yrow = Yp + (r0 + r)*XS + c;
        if (MODE == 3){
            float4 o = *(const float4*)yrow;
            vx += o.x; vy += o.y; vz += o.z; vw += o.w;
        }
        *(float4*)yrow = make_float4(vx, vy, vz, vw);
    }
}

// ======= smem-W GEMM: Y[r][c] (+)= sum_k X[r][k]*Ws[k][c], K=64 ======
// X broadcast (stride xstr), Ws lane-distinct cols (stride wstr), Y stride XS.
// MODE: 0 plain store, 3 accumulate
template<int MODE>
static __device__ __forceinline__ void mmT(
    const float* __restrict__ Xp, int xstr,
    const float* __restrict__ Wsp, int wstr,
    float* __restrict__ Yp)
{
    const int wid = threadIdx.x >> 5, lane = threadIdx.x & 31;
    const int r0 = wid << 3, c = lane << 2;
    unsigned long long acc[8][2];
#pragma unroll
    for (int r = 0; r < 8; ++r){ acc[r][0] = 0ull; acc[r][1] = 0ull; }
#pragma unroll 4
    for (int k = 0; k < 64; k += 4){
        float4 xq[8];
#pragma unroll
        for (int r = 0; r < 8; ++r)
            xq[r] = *(const float4*)(Xp + (r0 + r)*xstr + k);
#pragma unroll
        for (int u = 0; u < 4; ++u){
            ulonglong2 w = *(const ulonglong2*)(Wsp + (k + u)*wstr + c);
#pragma unroll
            for (int r = 0; r < 8; ++r){
                float xv = (u == 0) ? xq[r].x : (u == 1) ? xq[r].y : (u == 2) ? xq[r].z : xq[r].w;
                unsigned long long xx = pack2(xv);
                fma2(acc[r][0], w.x, xx);
                fma2(acc[r][1], w.y, xx);
            }
        }
    }
#pragma unroll
    for (int r = 0; r < 8; ++r){
        float2 p0 = unpack2(acc[r][0]);
        float2 p1 = unpack2(acc[r][1]);
        float vx = p0.x, vy = p0.y, vz = p1.x, vw = p1.y;
        float* yrow = Yp + (r0 + r)*XS + c;
        if (MODE == 3){
            float4 o = *(const float4*)yrow;
            vx += o.x; vy += o.y; vz += o.z; vw += o.w;
        }
        *(float4*)yrow = make_float4(vx, vy, vz, vw);
    }
}

// ===== S[i][j] = dot(T[i,:], E[j,:]) over 128 =====
static __device__ __forceinline__ void mm_s(
    const float* __restrict__ Tp, const float* __restrict__ Ep, float* __restrict__ Sp)
{
    const int wid = threadIdx.x >> 5, lane = threadIdx.x & 31;
    const int r0 = wid << 3;
    const int j0 = lane, j1 = lane + 32;
    unsigned long long acc[8][2];
#pragma unroll
    for (int r = 0; r < 8; ++r){ acc[r][0] = 0ull; acc[r][1] = 0ull; }
#pragma unroll 2
    for (int k = 0; k < 128; k += 4){
        ulonglong2 e0 = *(const ulonglong2*)(Ep + j0*XS + k);
        ulonglong2 e1 = *(const ulonglong2*)(Ep + j1*XS + k);
#pragma unroll
        for (int r = 0; r < 8; ++r){
            ulonglong2 tv = *(const ulonglong2*)(Tp + (r0 + r)*XS + k);
            fma2(acc[r][0], tv.x, e0.x);
            fma2(acc[r][0], tv.y, e0.y);
            fma2(acc[r][1], tv.x, e1.x);
            fma2(acc[r][1], tv.y, e1.y);
        }
    }
#pragma unroll
    for (int r = 0; r < 8; ++r){
        float2 p0 = unpack2(acc[r][0]);
        float2 p1 = unpack2(acc[r][1]);
        Sp[(r0 + r)*SS + j0] = p0.x + p0.y;
        Sp[(r0 + r)*SS + j1] = p1.x + p1.y;
    }
}

// ===== SimGNN attention pooling (mask all-ones -> denom 64), Xs row-major =====
static __device__ __forceinline__ void pool(
    const float* __restrict__ Xs, const float* __restrict__ Wp, float* __restrict__ out,
    float* __restrict__ mvec, float* __restrict__ ctxv, float* __restrict__ scores)
{
    const int t = threadIdx.x;
    const int wid = t >> 5, lane = t & 31;
    if (t < 128){
        float s = 0.f;
#pragma unroll 8
        for (int i = 0; i < 64; ++i) s += Xs[i*XS + t];
        mvec[t] = s * (1.0f / 64.0f);
    }
    __syncthreads();
    if (t < 128){
        float s = 0.f;
#pragma unroll 8
        for (int d = 0; d < 128; ++d) s += mvec[d] * Wp[d*128 + t];
        ctxv[t] = tanhf(s);
    }
    __syncthreads();
#pragma unroll
    for (int r = 0; r < 8; ++r){
        int row = wid*8 + r;
        float4 x4 = *(const float4*)(Xs + row*XS + (lane << 2));
        float4 c4 = *(const float4*)(ctxv + (lane << 2));
        float s = x4.x*c4.x + x4.y*c4.y + x4.z*c4.z + x4.w*c4.w;
#pragma unroll
        for (int o = 16; o; o >>= 1) s += __shfl_xor_sync(0xffffffffu, s, o);
        if (lane == 0) scores[row] = 1.0f / (1.0f + __expf(-s));
    }
    __syncthreads();
    if (t < 128){
        float g = 0.f;
#pragma unroll 8
        for (int i = 0; i < 64; ++i) g += Xs[i*XS + t] * scores[i];
        out[t] = g;
    }
}

__global__ void __launch_bounds__(NTHR, 1) CGFA_19533511262348_kernel(
    const float* __restrict__ A_src, const float* __restrict__ emb_src,
    const float* __restrict__ A_dst, const float* __restrict__ emb_dst,
    const float* __restrict__ Wa, const float* __restrict__ ba,
    const float* __restrict__ Wu, const float* __restrict__ bu,
    const float* __restrict__ Aff, const float* __restrict__ Wc, const float* __restrict__ bc,
    const float* __restrict__ Wp1, const float* __restrict__ Wp2,
    float* __restrict__ out)
{
    extern __shared__ float smf[];
    float* E1     = smf;                 // 64*132
    float* E2     = E1 + 64*XS;
    float* Tt     = E2 + 64*XS;
    float* Xs     = Tt + 64*XS;
    float* As     = Xs + 64*XS;          // 64*64
    float* Sm     = As + 64*64;          // 64*68
    float* S2     = Sm + 64*SS;          // 64*68
    float* Wbuf   = S2 + 64*SS;          // 3*2048
    float* colInv = Wbuf + 3*WST;        // 64
    float* rmax   = colInv + 64;
    float* rsumI  = rmax + 64;
    float* cmax   = rsumI + 64;
    float* csumI  = cmax + 64;
    float* mvec   = csumI + 64;          // 128
    float* ctxv   = mvec + 128;          // 128
    float* scores = ctxv + 128;          // 64

    const unsigned wbase = (unsigned)__cvta_generic_to_shared(Wbuf);
    const int b = blockIdx.x;
    const int t = threadIdx.x;
    const int wid = t >> 5, lane = t & 31;

    // ===== Siamese intra-graph conv =====
    for (int g = 0; g < 2; ++g){
        const float* Ain = g ? A_dst : A_src;
        const float* Ein = g ? emb_dst : emb_src;
        float* Eout = g ? E2 : E1;
        for (int e = t*4; e < 64*128; e += NTHR*4){
            float4 v = *(const float4*)(Ein + (size_t)b*64*128 + e);
            *(float4*)(Xs + (e >> 7)*XS + (e & 127)) = v;
        }
        for (int e = t*4; e < 64*64; e += NTHR*4)
            *(float4*)(As + e) = *(const float4*)(Ain + (size_t)b*64*64 + e);
        __syncthreads();
        if (t < 64){
            float s = 0.f;
#pragma unroll 8
            for (int i = 0; i < 64; ++i) s += As[i*64 + t];
            colInv[t] = 1.0f / fmaxf(s, 1e-12f);
        }
        __syncthreads();
        mmWstage<1>(Xs, Wu, bu, nullptr, Eout, Wbuf, wbase);   // relu(x@Wu+bu)
        mmWstage<2>(Xs, Wa, ba, colInv, Tt, Wbuf, wbase);      // relu(x@Wa+ba)*colInv[row]
        __syncthreads();
        mmT<3>(As, 64, Tt, XS, Eout);                          // Eout += A @ T
        __syncthreads();
    }

    // ===== affinity: S = (E1 @ Aff) @ E2^T =====
    mmWstage<0>(E1, Aff, nullptr, nullptr, Tt, Wbuf, wbase);
    __syncthreads();
    mm_s(Tt, E2, Sm);
    __syncthreads();

    // ===== bidirectional softmax stats, warp-parallel =====
#pragma unroll
    for (int r = 0; r < 8; ++r){
        int i = wid*8 + r;
        float a = Sm[i*SS + lane], bv = Sm[i*SS + lane + 32];
        float mx = fmaxf(a, bv);
#pragma unroll
        for (int o = 16; o; o >>= 1) mx = fmaxf(mx, __shfl_xor_sync(0xffffffffu, mx, o));
        float s = __expf(a - mx) + __expf(bv - mx);
#pragma unroll
        for (int o = 16; o; o >>= 1) s += __shfl_xor_sync(0xffffffffu, s, o);
        if (lane == 0){ rmax[i] = mx; rsumI[i] = 1.0f / s; }
    }
#pragma unroll
    for (int r = 0; r < 8; ++r){
        int j = wid*8 + r;
        float a = Sm[lane*SS + j], bv = Sm[(lane + 32)*SS + j];
        float mx = fmaxf(a, bv);
#pragma unroll
        for (int o = 16; o; o >>= 1) mx = fmaxf(mx, __shfl_xor_sync(0xffffffffu, mx, o));
        float s = __expf(a - mx) + __expf(bv - mx);
#pragma unroll
        for (int o = 16; o; o >>= 1) s += __shfl_xor_sync(0xffffffffu, s, o);
        if (lane == 0){ cmax[j] = mx; csumI[j] = 1.0f / s; }
    }
    __syncthreads();
    for (int e = t; e < 4096; e += NTHR){
        int i = e >> 6, j = e & 63;
        float v = Sm[i*SS + j];
        S2[j*SS + i] = __expf(v - cmax[j]) * csumI[j];   // col-softmax, transposed
        Sm[i*SS + j] = __expf(v - rmax[i]) * rsumI[i];   // row-softmax, in place
    }
    __syncthreads();

    // ===== new1 = [E1, Sm@E2] @ Wc + bc ; pool -> g1 =====
    mmT<0>(Sm, SS, E2, XS, Tt);                                   // att1
    __syncthreads();
    mmWstage<4>(E1, Wc, bc, nullptr, Xs, Wbuf, wbase);            // E1 @ Wc[:128] + bc
    mmWstage<3>(Tt, Wc + 128*128, nullptr, nullptr, Xs, Wbuf, wbase); // += att1 @ Wc[128:]
    __syncthreads();
    pool(Xs, Wp1, out + (size_t)b*128, mvec, ctxv, scores);
    __syncthreads();

    // ===== new2 = [E2, S2@E1] @ Wc + bc ; pool -> g2 =====
    mmT<0>(S2, SS, E1, XS, Tt);                                   // att2
    __syncthreads();
    mmWstage<4>(E2, Wc, bc, nullptr, Xs, Wbuf, wbase);
    mmWstage<3>(Tt, Wc + 128*128, nullptr, nullptr, Xs, Wbuf, wbase);
    __syncthreads();
    pool(Xs, Wp2, out + (size_t)(NB + b)*128, mvec, ctxv, scores);
}

extern "C" void kernel_launch(void* const* d_in, const int* in_sizes, int n_in,
                              void* d_out, int out_size)
{
    (void)in_sizes; (void)n_in; (void)out_size;
    const float* A_src   = (const float*)d_in[0];
    const float* emb_src = (const float*)d_in[1];
    // d_in[2] = mask_src (all ones, unused)
    const float* A_dst   = (const float*)d_in[3];
    const float* emb_dst = (const float*)d_in[4];
    // d_in[5] = mask_dst (all ones, unused)
    const float* Wa  = (const float*)d_in[6];
    const float* ba  = (const float*)d_in[7];
    const float* Wu  = (const float*)d_in[8];
    const float* bu  = (const float*)d_in[9];
    const float* Aff = (const float*)d_in[10];
    const float* Wc  = (const float*)d_in[11];
    const float* bc  = (const float*)d_in[12];
    const float* Wp1 = (const float*)d_in[13];
    const float* Wp2 = (const float*)d_in[14];
    float* out = (float*)d_out;

    const int smem_bytes = (64*XS*4 + 64*64 + 64*SS*2 + 3*WST + 64*5 + 128*2 + 64) * (int)sizeof(float);
    cudaFuncSetAttribute(CGFA_19533511262348_kernel,
                         cudaFuncAttributeMaxDynamicSharedMemorySize, smem_bytes);
    CGFA_19533511262348_kernel<<<NB, NTHR, smem_bytes>>>(
        A_src, emb_src, A_dst, emb_dst,
        Wa, ba, Wu, bu, Aff, Wc, bc, Wp1, Wp2, out);
}